// round 15
// baseline (speedup 1.0000x reference)
#include <cuda_runtime.h>

#define NN 50000
#define EE 800000
#define FF 602
#define HH 32
#define CC 41
#define BN_EPS 1e-5f
#define FULLMASK 0xffffffffu
#define NB_SCAN ((NN + 255) / 256)   // 196

#define KC 16                         // k-chunk for gemm1
#define GT2 64                        // rows per gemm1 block
#define XP 68                         // 64 + pad

#define NPB 64                        // nodes per gin/head block
#define NB_GIN ((NN + NPB - 1) / NPB) // 782

// ---------------- scratch (device globals) ----------------------------------
static __device__ float d_y  [NN * HH];
static __device__ float d_h1 [NN * HH];
static __device__ float d_h2 [NN * HH];
static __device__ float d_stats[4 * HH];
static __device__ int   d_counts[NN];     // zeroed by k_head each call (BSS=0 first call)
static __device__ int   d_rowptr[NN];
static __device__ int   d_cursor[NN];
static __device__ int   d_colsorted[EE];  // stores c*HH (pre-scaled)
static __device__ int   d_partsum[256];
static __device__ int   d_partflag[256];  // zeroed by k_head each call

// ---------------- K1: y = x @ W1a — 4x4 tile, double-buffered (round-11) ----
__global__ void __launch_bounds__(128) k_gemm1(const float* __restrict__ x,
                                               const float* __restrict__ W1a) {
    __shared__ float xs[2][KC][XP];
    __shared__ float Ws[2][KC][HH];

    const int tid = threadIdx.x;
    const int rg  = tid >> 3;             // 0..15 -> rows rg*4..rg*4+3
    const int cg  = (tid & 7) * 4;        // 0,4,...,28
    const int rowbase = blockIdx.x * GT2;

    const int kl = tid & 15;
    const int rl = tid >> 4;
    const int wk = tid >> 3;
    const int wc = (tid & 7) * 4;

    float acc[4][4];
#pragma unroll
    for (int i = 0; i < 4; i++)
#pragma unroll
        for (int j = 0; j < 4; j++) acc[i][j] = 0.f;

    float xr[8];
    float4 wr;

    {
        const bool kok = kl < FF;
#pragma unroll
        for (int p = 0; p < 8; p++) {
            int grow = rowbase + rl * 8 + p;
            xr[p] = (kok && grow < NN) ? x[(size_t)grow * FF + kl] : 0.f;
        }
        wr = (wk < FF) ? *(const float4*)&W1a[wk * HH + wc]
                       : make_float4(0.f, 0.f, 0.f, 0.f);
#pragma unroll
        for (int p = 0; p < 8; p++) xs[0][kl][rl * 8 + p] = xr[p];
        *(float4*)&Ws[0][wk][wc] = wr;
    }
    __syncthreads();

    int buf = 0;
    for (int kb = 0; kb < FF; kb += KC) {
        const int nb = kb + KC;
        const bool hasnext = nb < FF;
        if (hasnext) {
            const bool kok = (nb + kl) < FF;
#pragma unroll
            for (int p = 0; p < 8; p++) {
                int grow = rowbase + rl * 8 + p;
                xr[p] = (kok && grow < NN) ? x[(size_t)grow * FF + nb + kl] : 0.f;
            }
            wr = ((nb + wk) < FF) ? *(const float4*)&W1a[(nb + wk) * HH + wc]
                                  : make_float4(0.f, 0.f, 0.f, 0.f);
        }
#pragma unroll
        for (int k = 0; k < KC; k++) {
            float4 xv = *(const float4*)&xs[buf][k][rg * 4];
            float4 wv = *(const float4*)&Ws[buf][k][cg];
            acc[0][0] += xv.x * wv.x; acc[0][1] += xv.x * wv.y;
            acc[0][2] += xv.x * wv.z; acc[0][3] += xv.x * wv.w;
            acc[1][0] += xv.y * wv.x; acc[1][1] += xv.y * wv.y;
            acc[1][2] += xv.y * wv.z; acc[1][3] += xv.y * wv.w;
            acc[2][0] += xv.z * wv.x; acc[2][1] += xv.z * wv.y;
            acc[2][2] += xv.z * wv.z; acc[2][3] += xv.z * wv.w;
            acc[3][0] += xv.w * wv.x; acc[3][1] += xv.w * wv.y;
            acc[3][2] += xv.w * wv.z; acc[3][3] += xv.w * wv.w;
        }
        if (hasnext) {
            int nbuf = buf ^ 1;
#pragma unroll
            for (int p = 0; p < 8; p++) xs[nbuf][kl][rl * 8 + p] = xr[p];
            *(float4*)&Ws[nbuf][wk][wc] = wr;
            __syncthreads();
            buf = nbuf;
        }
    }
#pragma unroll
    for (int i = 0; i < 4; i++) {
        int row = rowbase + rg * 4 + i;
        if (row < NN)
            *(float4*)&d_y[(size_t)row * HH + cg] =
                make_float4(acc[i][0], acc[i][1], acc[i][2], acc[i][3]);
    }
}

// ---------------- CSR build: 1 edge/thread -----------------------------------
__global__ void k_hist(const int* __restrict__ row) {
    int e = blockIdx.x * 256 + threadIdx.x;
    if (e < EE) atomicAdd(&d_counts[row[e]], 1);
}

// merged scan: local Hillis-Steele + parallel spin on lower block partials.
__global__ void k_scan() {
    __shared__ int sh[256];
    __shared__ int red[8];
    __shared__ int s_boff;
    const int tid = threadIdx.x, blk = blockIdx.x;

    if (blk == 0 && tid < 4 * HH) d_stats[tid] = 0.f;

    int i = blk * 256 + tid;
    int c = (i < NN) ? d_counts[i] : 0;
    sh[tid] = c;
    __syncthreads();
    for (int off = 1; off < 256; off <<= 1) {
        int t = (tid >= off) ? sh[tid - off] : 0;
        __syncthreads();
        sh[tid] += t;
        __syncthreads();
    }
    if (tid == 0) {
        d_partsum[blk] = sh[255];
        __threadfence();
        d_partflag[blk] = 1;
    }
    int acc = 0;
    for (int b = tid; b < blk; b += 256) {
        while (((volatile int*)d_partflag)[b] == 0) { }
        acc += ((volatile int*)d_partsum)[b];
    }
#pragma unroll
    for (int off = 16; off > 0; off >>= 1)
        acc += __shfl_down_sync(FULLMASK, acc, off);
    if ((tid & 31) == 0) red[tid >> 5] = acc;
    __syncthreads();
    if (tid == 0) {
        int t = 0;
#pragma unroll
        for (int w = 0; w < 8; w++) t += red[w];
        s_boff = t;
    }
    __syncthreads();
    int start = s_boff + sh[tid] - c;
    if (i < NN) { d_rowptr[i] = start; d_cursor[i] = start; }
}

__global__ void k_scatter(const int* __restrict__ row, const int* __restrict__ col) {
    int e = blockIdx.x * 256 + threadIdx.x;
    if (e >= EE) return;
    int r = row[e];
    int c = col[e];
    int p = atomicAdd(&d_cursor[r], 1);
    d_colsorted[p] = c * HH;              // pre-scaled
}

// ---------------- gather (warp per node, lane = feature; 8-wide MLP) --------
__device__ __forceinline__ float gather_raw(const float* __restrict__ src,
                                            int s0, int deg, int lane) {
    float acc = 0.f;
    for (int e0 = 0; e0 < deg; e0 += 32) {
        int rem = deg - e0;
        if (rem > 32) rem = 32;
        int idx = (lane < rem) ? d_colsorted[s0 + e0 + lane] : 0;  // c*HH
        int j = 0;
        for (; j + 8 <= rem; j += 8) {
            int c0 = __shfl_sync(FULLMASK, idx, j);
            int c1 = __shfl_sync(FULLMASK, idx, j + 1);
            int c2 = __shfl_sync(FULLMASK, idx, j + 2);
            int c3 = __shfl_sync(FULLMASK, idx, j + 3);
            int c4 = __shfl_sync(FULLMASK, idx, j + 4);
            int c5 = __shfl_sync(FULLMASK, idx, j + 5);
            int c6 = __shfl_sync(FULLMASK, idx, j + 6);
            int c7 = __shfl_sync(FULLMASK, idx, j + 7);
            float v0 = src[c0 + lane];
            float v1 = src[c1 + lane];
            float v2 = src[c2 + lane];
            float v3 = src[c3 + lane];
            float v4 = src[c4 + lane];
            float v5 = src[c5 + lane];
            float v6 = src[c6 + lane];
            float v7 = src[c7 + lane];
            acc += v0; acc += v1; acc += v2; acc += v3;
            acc += v4; acc += v5; acc += v6; acc += v7;
        }
        for (; j < rem; j++) {
            int c = __shfl_sync(FULLMASK, idx, j);
            acc += src[c + lane];
        }
    }
    return acc;
}

// tiled matvec: thread owns (node nl, cols cg..cg+7), z staged [k][node]
__device__ __forceinline__ void matmul8(const float (*zst)[NPB + 1],
                                        const float (*Ws)[HH],
                                        int nl, int cg, float o[8]) {
#pragma unroll
    for (int k = 0; k < HH; k++) {
        float zv = zst[k][nl];
        float4 w0 = *(const float4*)&Ws[k][cg];
        float4 w1 = *(const float4*)&Ws[k][cg + 4];
        o[0] += zv * w0.x; o[1] += zv * w0.y;
        o[2] += zv * w0.z; o[3] += zv * w0.w;
        o[4] += zv * w1.x; o[5] += zv * w1.y;
        o[6] += zv * w1.z; o[7] += zv * w1.w;
    }
}

__device__ __forceinline__ void stats_reduce(float o[8], bool valid,
                                             float (*redS)[HH], float (*redQ)[HH],
                                             int warp, int lane, float* gS, float* gQ) {
    float s[8], q[8];
#pragma unroll
    for (int j = 0; j < 8; j++) {
        float v = valid ? o[j] : 0.f;
        s[j] = v; q[j] = v * v;
    }
#pragma unroll
    for (int off = 16; off >= 4; off >>= 1)
#pragma unroll
        for (int j = 0; j < 8; j++) {
            s[j] += __shfl_down_sync(FULLMASK, s[j], off);
            q[j] += __shfl_down_sync(FULLMASK, q[j], off);
        }
    if (lane < 4) {
#pragma unroll
        for (int j = 0; j < 8; j++) {
            redS[warp][lane * 8 + j] = s[j];
            redQ[warp][lane * 8 + j] = q[j];
        }
    }
    __syncthreads();
    if (warp == 0) {
        float ts = 0.f, tq = 0.f;
#pragma unroll
        for (int w = 0; w < 8; w++) { ts += redS[w][lane]; tq += redQ[w][lane]; }
        atomicAdd(&gS[lane], ts);
        atomicAdd(&gQ[lane], tq);
    }
}

// conv1
__global__ void __launch_bounds__(256) k_gin1(
    const float* __restrict__ ba, const float* __restrict__ Wb,
    const float* __restrict__ bb) {
    __shared__ float zst[HH][NPB + 1];
    __shared__ __align__(16) float Ws[HH][HH];
    __shared__ float redS[8][HH], redQ[8][HH];

    const int tid = threadIdx.x;
    const int warp = tid >> 5, lane = tid & 31;
    const int base = blockIdx.x * NPB;

    for (int i = tid; i < HH * HH; i += 256) Ws[i >> 5][i & 31] = Wb[i];

    const float baL = ba[lane];
#pragma unroll
    for (int i = 0; i < 8; i++) {
        int nl = warp * 8 + i;
        int n = base + nl;
        float z = 0.f;
        if (n < NN) {
            int s0 = d_rowptr[n], deg = d_counts[n];
            float acc = gather_raw(d_y, s0, deg, lane);
            z = fmaxf(d_y[(size_t)n * HH + lane] + acc + baL, 0.f);
        }
        zst[lane][nl] = z;
    }
    __syncthreads();

    const int nl = tid >> 2;
    const int cg = (tid & 3) * 8;
    const int n = base + nl;
    const bool valid = n < NN;

    float o[8];
    float4 b0 = *(const float4*)&bb[cg];
    float4 b1 = *(const float4*)&bb[cg + 4];
    o[0] = b0.x; o[1] = b0.y; o[2] = b0.z; o[3] = b0.w;
    o[4] = b1.x; o[5] = b1.y; o[6] = b1.z; o[7] = b1.w;
    matmul8(zst, Ws, nl, cg, o);

    if (valid) {
        *(float4*)&d_h1[(size_t)n * HH + cg]     = make_float4(o[0], o[1], o[2], o[3]);
        *(float4*)&d_h1[(size_t)n * HH + cg + 4] = make_float4(o[4], o[5], o[6], o[7]);
    }
    stats_reduce(o, valid, redS, redQ, warp, lane, &d_stats[0], &d_stats[HH]);
}

// conv2
__global__ void __launch_bounds__(256) k_gin2(
    const float* __restrict__ g1, const float* __restrict__ be1,
    const float* __restrict__ Wa, const float* __restrict__ ba,
    const float* __restrict__ Wb, const float* __restrict__ bb) {
    __shared__ float zst[HH][NPB + 1];
    __shared__ float ust[HH][NPB + 1];
    __shared__ __align__(16) float Wsa[HH][HH];
    __shared__ __align__(16) float Wsb[HH][HH];
    __shared__ float redS[8][HH], redQ[8][HH];

    const int tid = threadIdx.x;
    const int warp = tid >> 5, lane = tid & 31;
    const int base = blockIdx.x * NPB;

    for (int i = tid; i < HH * HH; i += 256) {
        Wsa[i >> 5][i & 31] = Wa[i];
        Wsb[i >> 5][i & 31] = Wb[i];
    }

    float m = d_stats[lane] * (1.f / NN);
    float v = d_stats[HH + lane] * (1.f / NN) - m * m;
    float scale = g1[lane] * rsqrtf(v + BN_EPS);
    float shift = be1[lane] - m * scale;

#pragma unroll
    for (int i = 0; i < 8; i++) {
        int nl = warp * 8 + i;
        int n = base + nl;
        float t = 0.f;
        if (n < NN) {
            int s0 = d_rowptr[n], deg = d_counts[n];
            float raw = gather_raw(d_h1, s0, deg, lane);
            raw += d_h1[(size_t)n * HH + lane];
            t = raw * scale + (float)(deg + 1) * shift;
        }
        zst[lane][nl] = t;
    }
    __syncthreads();

    const int nl = tid >> 2;
    const int cg = (tid & 3) * 8;
    const int n = base + nl;
    const bool valid = n < NN;

    float u[8];
    {
        float4 b0 = *(const float4*)&ba[cg];
        float4 b1 = *(const float4*)&ba[cg + 4];
        u[0] = b0.x; u[1] = b0.y; u[2] = b0.z; u[3] = b0.w;
        u[4] = b1.x; u[5] = b1.y; u[6] = b1.z; u[7] = b1.w;
    }
    matmul8(zst, Wsa, nl, cg, u);
#pragma unroll
    for (int j = 0; j < 8; j++) {
        u[j] = fmaxf(u[j], 0.f);
        ust[cg + j][nl] = u[j];
    }
    __syncthreads();

    float o[8];
    {
        float4 b0 = *(const float4*)&bb[cg];
        float4 b1 = *(const float4*)&bb[cg + 4];
        o[0] = b0.x; o[1] = b0.y; o[2] = b0.z; o[3] = b0.w;
        o[4] = b1.x; o[5] = b1.y; o[6] = b1.z; o[7] = b1.w;
    }
    matmul8(ust, Wsb, nl, cg, o);

    if (valid) {
        *(float4*)&d_h2[(size_t)n * HH + cg]     = make_float4(o[0], o[1], o[2], o[3]);
        *(float4*)&d_h2[(size_t)n * HH + cg + 4] = make_float4(o[4], o[5], o[6], o[7]);
    }
    stats_reduce(o, valid, redS, redQ, warp, lane, &d_stats[2 * HH], &d_stats[3 * HH]);
}

// head (+ re-zero CSR state for next call)
__global__ void __launch_bounds__(256) k_head(
    const float* __restrict__ Wf1, const float* __restrict__ bf1,
    const float* __restrict__ Wf2, const float* __restrict__ bf2,
    const float* __restrict__ g2, const float* __restrict__ be2,
    float* __restrict__ outp) {
    __shared__ float gst[HH][NPB + 1];
    __shared__ float ust[HH][NPB + 1];
    __shared__ __align__(16) float W1s[HH][HH];
    __shared__ __align__(16) float W2s[HH][48];
    __shared__ float scl[HH], shf[HH];

    const int tid = threadIdx.x;
    const int base = blockIdx.x * NPB;

    {
        int g = blockIdx.x * 256 + tid;
        if (g < NN) d_counts[g] = 0;
        if (g < 256) d_partflag[g] = 0;
    }

    for (int i = tid; i < HH * HH; i += 256) W1s[i >> 5][i & 31] = Wf1[i];
    for (int i = tid; i < HH * 48; i += 256) {
        int k = i / 48, c = i % 48;
        W2s[k][c] = (c < CC) ? Wf2[k * CC + c] : 0.f;
    }
    if (tid < HH) {
        float m = d_stats[2 * HH + tid] * (1.f / NN);
        float v = d_stats[3 * HH + tid] * (1.f / NN) - m * m;
        float s = g2[tid] * rsqrtf(v + BN_EPS);
        scl[tid] = s;
        shf[tid] = be2[tid] - m * s;
    }
    __syncthreads();

    const int nl = tid >> 2;
    const int cg = (tid & 3) * 8;
    const int n = base + nl;
    const bool valid = n < NN;

    {
        float4 h0 = make_float4(0.f, 0.f, 0.f, 0.f), h1v = h0;
        if (valid) {
            h0  = *(const float4*)&d_h2[(size_t)n * HH + cg];
            h1v = *(const float4*)&d_h2[(size_t)n * HH + cg + 4];
        }
        gst[cg + 0][nl] = h0.x  * scl[cg + 0] + shf[cg + 0];
        gst[cg + 1][nl] = h0.y  * scl[cg + 1] + shf[cg + 1];
        gst[cg + 2][nl] = h0.z  * scl[cg + 2] + shf[cg + 2];
        gst[cg + 3][nl] = h0.w  * scl[cg + 3] + shf[cg + 3];
        gst[cg + 4][nl] = h1v.x * scl[cg + 4] + shf[cg + 4];
        gst[cg + 5][nl] = h1v.y * scl[cg + 5] + shf[cg + 5];
        gst[cg + 6][nl] = h1v.z * scl[cg + 6] + shf[cg + 6];
        gst[cg + 7][nl] = h1v.w * scl[cg + 7] + shf[cg + 7];
    }
    __syncthreads();

    float u[8];
    {
        float4 b0 = *(const float4*)&bf1[cg];
        float4 b1 = *(const float4*)&bf1[cg + 4];
        u[0] = b0.x; u[1] = b0.y; u[2] = b0.z; u[3] = b0.w;
        u[4] = b1.x; u[5] = b1.y; u[6] = b1.z; u[7] = b1.w;
    }
    matmul8(gst, W1s, nl, cg, u);
#pragma unroll
    for (int j = 0; j < 8; j++) {
        u[j] = fmaxf(u[j], 0.f);
        ust[cg + j][nl] = u[j];
    }
    __syncthreads();

    const int cg2 = 32 + cg;
    const bool sec = (tid & 3) < 2;
    float o[8], o2[8];
#pragma unroll
    for (int j = 0; j < 8; j++) {
        int c = cg + j;
        o[j] = (c < CC) ? bf2[c] : 0.f;
        int c2 = cg2 + j;
        o2[j] = (sec && c2 < CC) ? bf2[c2] : 0.f;
    }
#pragma unroll
    for (int k = 0; k < HH; k++) {
        float zv = ust[k][nl];
        float4 w0 = *(const float4*)&W2s[k][cg];
        float4 w1 = *(const float4*)&W2s[k][cg + 4];
        o[0] += zv * w0.x; o[1] += zv * w0.y;
        o[2] += zv * w0.z; o[3] += zv * w0.w;
        o[4] += zv * w1.x; o[5] += zv * w1.y;
        o[6] += zv * w1.z; o[7] += zv * w1.w;
        if (sec) {
            float4 s0 = *(const float4*)&W2s[k][cg2];
            float4 s1 = *(const float4*)&W2s[k][cg2 + 4];
            o2[0] += zv * s0.x; o2[1] += zv * s0.y;
            o2[2] += zv * s0.z; o2[3] += zv * s0.w;
            o2[4] += zv * s1.x; o2[5] += zv * s1.y;
            o2[6] += zv * s1.z; o2[7] += zv * s1.w;
        }
    }
    if (valid) {
#pragma unroll
        for (int j = 0; j < 8; j++)
            outp[(size_t)n * CC + cg + j] = o[j];
        if (sec) {
#pragma unroll
            for (int j = 0; j < 8; j++) {
                int c2 = cg2 + j;
                if (c2 < CC) outp[(size_t)n * CC + c2] = o2[j];
            }
        }
    }
}

// ---------------- launcher ----------------------------------------------------
extern "C" void kernel_launch(void* const* d_in, const int* in_sizes, int n_in,
                              void* d_out, int out_size) {
    const float* x   = (const float*)d_in[0];
    const int*   row = (const int*)  d_in[1];
    const int*   col = (const int*)  d_in[2];
    const float* W1a = (const float*)d_in[3];
    const float* b1a = (const float*)d_in[4];
    const float* W1b = (const float*)d_in[5];
    const float* b1b = (const float*)d_in[6];
    const float* g1  = (const float*)d_in[7];
    const float* be1 = (const float*)d_in[8];
    const float* W2a = (const float*)d_in[9];
    const float* b2a = (const float*)d_in[10];
    const float* W2b = (const float*)d_in[11];
    const float* b2b = (const float*)d_in[12];
    const float* g2  = (const float*)d_in[13];
    const float* be2 = (const float*)d_in[14];
    const float* Wf1 = (const float*)d_in[15];
    const float* bf1 = (const float*)d_in[16];
    const float* Wf2 = (const float*)d_in[17];
    const float* bf2 = (const float*)d_in[18];
    float* out = (float*)d_out;

    static cudaStream_t sA = nullptr;
    static cudaEvent_t  evFork = nullptr, evJoin = nullptr;
    static bool inited = false;
    if (!inited) {
        cudaStreamCreateWithFlags(&sA, cudaStreamNonBlocking);
        cudaEventCreateWithFlags(&evFork, cudaEventDisableTiming);
        cudaEventCreateWithFlags(&evJoin, cudaEventDisableTiming);
        inited = true;
    }

    // fork: gemm1 (long pole) enqueued FIRST on sA; CSR build on main stream
    cudaEventRecord(evFork, 0);
    cudaStreamWaitEvent(sA, evFork, 0);

    k_gemm1<<<(NN + GT2 - 1) / GT2, 128, 0, sA>>>(x, W1a);

    const int eblk1 = (EE + 255) / 256;
    k_hist   <<<eblk1, 256, 0, 0>>>(row);
    k_scan   <<<NB_SCAN, 256, 0, 0>>>();
    k_scatter<<<eblk1, 256, 0, 0>>>(row, col);

    // join
    cudaEventRecord(evJoin, sA);
    cudaStreamWaitEvent(0, evJoin, 0);

    k_gin1<<<NB_GIN, 256, 0, 0>>>(b1a, W1b, b1b);
    k_gin2<<<NB_GIN, 256, 0, 0>>>(g1, be1, W2a, b2a, W2b, b2b);
    k_head<<<NB_GIN, 256, 0, 0>>>(Wf1, bf1, Wf2, bf2, g2, be2, out);
}

// round 16
// speedup vs baseline: 1.0647x; 1.0647x over previous
#include <cuda_runtime.h>

#define NN 50000
#define EE 800000
#define FF 602
#define HH 32
#define CC 41
#define BN_EPS 1e-5f
#define FULLMASK 0xffffffffu
#define NB_SCAN ((NN + 255) / 256)   // 196

#define KC 16                         // k-chunk for gemm1
#define GT2 64                        // rows per gemm1 block
#define XP 68                         // 64 + pad

#define NPB 64                        // nodes per gin/head block
#define NB_GIN ((NN + NPB - 1) / NPB) // 782
#define SCAP 2048                     // staged edge-index capacity per tile (8KB)

// ---------------- scratch (device globals) ----------------------------------
static __device__ float d_y  [NN * HH];
static __device__ float d_h1 [NN * HH];
static __device__ float d_h2 [NN * HH];
static __device__ float d_stats[4 * HH];
static __device__ int   d_counts[NN];     // zeroed by k_head each call (BSS=0 first call)
static __device__ int   d_rowptr[NN];
static __device__ int   d_cursor[NN];
static __device__ int   d_colsorted[EE];  // stores c*HH (pre-scaled)
static __device__ int   d_partsum[256];
static __device__ int   d_partflag[256];  // zeroed by k_head each call

// ---------------- K1: y = x @ W1a — 4x4 tile, double-buffered (round-11) ----
__global__ void __launch_bounds__(128) k_gemm1(const float* __restrict__ x,
                                               const float* __restrict__ W1a) {
    __shared__ float xs[2][KC][XP];
    __shared__ float Ws[2][KC][HH];

    const int tid = threadIdx.x;
    const int rg  = tid >> 3;             // 0..15 -> rows rg*4..rg*4+3
    const int cg  = (tid & 7) * 4;        // 0,4,...,28
    const int rowbase = blockIdx.x * GT2;

    const int kl = tid & 15;
    const int rl = tid >> 4;
    const int wk = tid >> 3;
    const int wc = (tid & 7) * 4;

    float acc[4][4];
#pragma unroll
    for (int i = 0; i < 4; i++)
#pragma unroll
        for (int j = 0; j < 4; j++) acc[i][j] = 0.f;

    float xr[8];
    float4 wr;

    {
        const bool kok = kl < FF;
#pragma unroll
        for (int p = 0; p < 8; p++) {
            int grow = rowbase + rl * 8 + p;
            xr[p] = (kok && grow < NN) ? x[(size_t)grow * FF + kl] : 0.f;
        }
        wr = (wk < FF) ? *(const float4*)&W1a[wk * HH + wc]
                       : make_float4(0.f, 0.f, 0.f, 0.f);
#pragma unroll
        for (int p = 0; p < 8; p++) xs[0][kl][rl * 8 + p] = xr[p];
        *(float4*)&Ws[0][wk][wc] = wr;
    }
    __syncthreads();

    int buf = 0;
    for (int kb = 0; kb < FF; kb += KC) {
        const int nb = kb + KC;
        const bool hasnext = nb < FF;
        if (hasnext) {
            const bool kok = (nb + kl) < FF;
#pragma unroll
            for (int p = 0; p < 8; p++) {
                int grow = rowbase + rl * 8 + p;
                xr[p] = (kok && grow < NN) ? x[(size_t)grow * FF + nb + kl] : 0.f;
            }
            wr = ((nb + wk) < FF) ? *(const float4*)&W1a[(nb + wk) * HH + wc]
                                  : make_float4(0.f, 0.f, 0.f, 0.f);
        }
#pragma unroll
        for (int k = 0; k < KC; k++) {
            float4 xv = *(const float4*)&xs[buf][k][rg * 4];
            float4 wv = *(const float4*)&Ws[buf][k][cg];
            acc[0][0] += xv.x * wv.x; acc[0][1] += xv.x * wv.y;
            acc[0][2] += xv.x * wv.z; acc[0][3] += xv.x * wv.w;
            acc[1][0] += xv.y * wv.x; acc[1][1] += xv.y * wv.y;
            acc[1][2] += xv.y * wv.z; acc[1][3] += xv.y * wv.w;
            acc[2][0] += xv.z * wv.x; acc[2][1] += xv.z * wv.y;
            acc[2][2] += xv.z * wv.z; acc[2][3] += xv.z * wv.w;
            acc[3][0] += xv.w * wv.x; acc[3][1] += xv.w * wv.y;
            acc[3][2] += xv.w * wv.z; acc[3][3] += xv.w * wv.w;
        }
        if (hasnext) {
            int nbuf = buf ^ 1;
#pragma unroll
            for (int p = 0; p < 8; p++) xs[nbuf][kl][rl * 8 + p] = xr[p];
            *(float4*)&Ws[nbuf][wk][wc] = wr;
            __syncthreads();
            buf = nbuf;
        }
    }
#pragma unroll
    for (int i = 0; i < 4; i++) {
        int row = rowbase + rg * 4 + i;
        if (row < NN)
            *(float4*)&d_y[(size_t)row * HH + cg] =
                make_float4(acc[i][0], acc[i][1], acc[i][2], acc[i][3]);
    }
}

// ---------------- CSR build: 1 edge/thread -----------------------------------
__global__ void k_hist(const int* __restrict__ row) {
    int e = blockIdx.x * 256 + threadIdx.x;
    if (e < EE) atomicAdd(&d_counts[row[e]], 1);
}

// merged scan: local Hillis-Steele + parallel spin on lower block partials.
__global__ void k_scan() {
    __shared__ int sh[256];
    __shared__ int red[8];
    __shared__ int s_boff;
    const int tid = threadIdx.x, blk = blockIdx.x;

    if (blk == 0 && tid < 4 * HH) d_stats[tid] = 0.f;

    int i = blk * 256 + tid;
    int c = (i < NN) ? d_counts[i] : 0;
    sh[tid] = c;
    __syncthreads();
    for (int off = 1; off < 256; off <<= 1) {
        int t = (tid >= off) ? sh[tid - off] : 0;
        __syncthreads();
        sh[tid] += t;
        __syncthreads();
    }
    if (tid == 0) {
        d_partsum[blk] = sh[255];
        __threadfence();
        d_partflag[blk] = 1;
    }
    int acc = 0;
    for (int b = tid; b < blk; b += 256) {
        while (((volatile int*)d_partflag)[b] == 0) { }
        acc += ((volatile int*)d_partsum)[b];
    }
#pragma unroll
    for (int off = 16; off > 0; off >>= 1)
        acc += __shfl_down_sync(FULLMASK, acc, off);
    if ((tid & 31) == 0) red[tid >> 5] = acc;
    __syncthreads();
    if (tid == 0) {
        int t = 0;
#pragma unroll
        for (int w = 0; w < 8; w++) t += red[w];
        s_boff = t;
    }
    __syncthreads();
    int start = s_boff + sh[tid] - c;
    if (i < NN) { d_rowptr[i] = start; d_cursor[i] = start; }
}

__global__ void k_scatter(const int* __restrict__ row, const int* __restrict__ col) {
    int e = blockIdx.x * 256 + threadIdx.x;
    if (e >= EE) return;
    int r = row[e];
    int c = col[e];
    int p = atomicAdd(&d_cursor[r], 1);
    d_colsorted[p] = c * HH;              // pre-scaled
}

// ---------------- gather: smem-staged indices (no shfl) ----------------------
__device__ __forceinline__ float gather_fast(const float* __restrict__ src,
                                             const int* __restrict__ sidx,
                                             int deg, int lane) {
    float acc = 0.f;
    int j = 0;
    for (; j + 4 <= deg; j += 4) {
        int c0 = sidx[j];
        int c1 = sidx[j + 1];
        int c2 = sidx[j + 2];
        int c3 = sidx[j + 3];
        acc += src[c0 + lane];
        acc += src[c1 + lane];
        acc += src[c2 + lane];
        acc += src[c3 + lane];
    }
    for (; j < deg; j++)
        acc += src[sidx[j] + lane];
    return acc;
}

// fallback (tile edge count > SCAP; statistically unreachable, correctness-safe)
__device__ __forceinline__ float gather_slow(const float* __restrict__ src,
                                             int s0, int deg, int lane) {
    float acc = 0.f;
    for (int j = 0; j < deg; j++)
        acc += src[d_colsorted[s0 + j] + lane];
    return acc;
}

// tiled matvec: thread owns (node nl, cols cg..cg+7), z staged [k][node]
__device__ __forceinline__ void matmul8(const float (*zst)[NPB + 1],
                                        const float (*Ws)[HH],
                                        int nl, int cg, float o[8]) {
#pragma unroll
    for (int k = 0; k < HH; k++) {
        float zv = zst[k][nl];
        float4 w0 = *(const float4*)&Ws[k][cg];
        float4 w1 = *(const float4*)&Ws[k][cg + 4];
        o[0] += zv * w0.x; o[1] += zv * w0.y;
        o[2] += zv * w0.z; o[3] += zv * w0.w;
        o[4] += zv * w1.x; o[5] += zv * w1.y;
        o[6] += zv * w1.z; o[7] += zv * w1.w;
    }
}

// stats reduce into reused smem (caller must __syncthreads() before this)
__device__ __forceinline__ void stats_reduce(float o[8], bool valid,
                                             float* redS, float* redQ,
                                             int warp, int lane,
                                             float* gS, float* gQ) {
    float s[8], q[8];
#pragma unroll
    for (int j = 0; j < 8; j++) {
        float v = valid ? o[j] : 0.f;
        s[j] = v; q[j] = v * v;
    }
#pragma unroll
    for (int off = 16; off >= 4; off >>= 1)
#pragma unroll
        for (int j = 0; j < 8; j++) {
            s[j] += __shfl_down_sync(FULLMASK, s[j], off);
            q[j] += __shfl_down_sync(FULLMASK, q[j], off);
        }
    if (lane < 4) {
#pragma unroll
        for (int j = 0; j < 8; j++) {
            redS[warp * HH + lane * 8 + j] = s[j];
            redQ[warp * HH + lane * 8 + j] = q[j];
        }
    }
    __syncthreads();
    if (warp == 0) {
        float ts = 0.f, tq = 0.f;
#pragma unroll
        for (int w = 0; w < 8; w++) { ts += redS[w * HH + lane]; tq += redQ[w * HH + lane]; }
        atomicAdd(&gS[lane], ts);
        atomicAdd(&gQ[lane], tq);
    }
}

// conv1: h1 = relu(y[n] + agg(y) + b1a) @ W1b + b1b ; stats1
__global__ void __launch_bounds__(256) k_gin1(
    const float* __restrict__ ba, const float* __restrict__ Wb,
    const float* __restrict__ bb) {
    __shared__ float zst[HH][NPB + 1];
    __shared__ __align__(16) float Ws[HH][HH];
    __shared__ int sidx[SCAP];

    const int tid = threadIdx.x;
    const int warp = tid >> 5, lane = tid & 31;
    const int base = blockIdx.x * NPB;

    for (int i = tid; i < HH * HH; i += 256) Ws[i >> 5][i & 31] = Wb[i];

    // stage tile edge indices (contiguous CSR range)
    const int e_start = d_rowptr[base];
    const int last = (base + NPB < NN) ? (base + NPB) : NN;
    const int e_end = (last < NN) ? d_rowptr[last] : EE;
    const int cnt = min(e_end - e_start, SCAP);
    for (int i = tid; i < cnt; i += 256) sidx[i] = d_colsorted[e_start + i];
    __syncthreads();

    const float baL = ba[lane];
#pragma unroll
    for (int i = 0; i < 8; i++) {
        int nl = warp * 8 + i;
        int n = base + nl;
        float z = 0.f;
        if (n < NN) {
            int s0 = d_rowptr[n], deg = d_counts[n];
            int off = s0 - e_start;
            float acc = (off + deg <= cnt) ? gather_fast(d_y, sidx + off, deg, lane)
                                           : gather_slow(d_y, s0, deg, lane);
            z = fmaxf(d_y[(size_t)n * HH + lane] + acc + baL, 0.f);
        }
        zst[lane][nl] = z;
    }
    __syncthreads();

    const int nl = tid >> 2;
    const int cg = (tid & 3) * 8;
    const int n = base + nl;
    const bool valid = n < NN;

    float o[8];
    float4 b0 = *(const float4*)&bb[cg];
    float4 b1 = *(const float4*)&bb[cg + 4];
    o[0] = b0.x; o[1] = b0.y; o[2] = b0.z; o[3] = b0.w;
    o[4] = b1.x; o[5] = b1.y; o[6] = b1.z; o[7] = b1.w;
    matmul8(zst, Ws, nl, cg, o);

    if (valid) {
        *(float4*)&d_h1[(size_t)n * HH + cg]     = make_float4(o[0], o[1], o[2], o[3]);
        *(float4*)&d_h1[(size_t)n * HH + cg + 4] = make_float4(o[4], o[5], o[6], o[7]);
    }
    __syncthreads();   // zst free -> reuse for stats reduction
    stats_reduce(o, valid, &zst[0][0], &zst[8][0], warp, lane,
                 &d_stats[0], &d_stats[HH]);
}

// conv2: BN1 folded; h2 = relu((t)@W2a+b2a)@W2b+b2b ; stats2
__global__ void __launch_bounds__(256) k_gin2(
    const float* __restrict__ g1, const float* __restrict__ be1,
    const float* __restrict__ Wa, const float* __restrict__ ba,
    const float* __restrict__ Wb, const float* __restrict__ bb) {
    __shared__ float zst[HH][NPB + 1];
    __shared__ float ust[HH][NPB + 1];
    __shared__ __align__(16) float Wsa[HH][HH];
    __shared__ __align__(16) float Wsb[HH][HH];
    __shared__ int sidx[SCAP];

    const int tid = threadIdx.x;
    const int warp = tid >> 5, lane = tid & 31;
    const int base = blockIdx.x * NPB;

    for (int i = tid; i < HH * HH; i += 256) {
        Wsa[i >> 5][i & 31] = Wa[i];
        Wsb[i >> 5][i & 31] = Wb[i];
    }

    const int e_start = d_rowptr[base];
    const int last = (base + NPB < NN) ? (base + NPB) : NN;
    const int e_end = (last < NN) ? d_rowptr[last] : EE;
    const int cnt = min(e_end - e_start, SCAP);
    for (int i = tid; i < cnt; i += 256) sidx[i] = d_colsorted[e_start + i];
    __syncthreads();

    float m = d_stats[lane] * (1.f / NN);
    float v = d_stats[HH + lane] * (1.f / NN) - m * m;
    float scale = g1[lane] * rsqrtf(v + BN_EPS);
    float shift = be1[lane] - m * scale;

#pragma unroll
    for (int i = 0; i < 8; i++) {
        int nl = warp * 8 + i;
        int n = base + nl;
        float t = 0.f;
        if (n < NN) {
            int s0 = d_rowptr[n], deg = d_counts[n];
            int off = s0 - e_start;
            float raw = (off + deg <= cnt) ? gather_fast(d_h1, sidx + off, deg, lane)
                                           : gather_slow(d_h1, s0, deg, lane);
            raw += d_h1[(size_t)n * HH + lane];
            t = raw * scale + (float)(deg + 1) * shift;
        }
        zst[lane][nl] = t;
    }
    __syncthreads();

    const int nl = tid >> 2;
    const int cg = (tid & 3) * 8;
    const int n = base + nl;
    const bool valid = n < NN;

    float u[8];
    {
        float4 b0 = *(const float4*)&ba[cg];
        float4 b1 = *(const float4*)&ba[cg + 4];
        u[0] = b0.x; u[1] = b0.y; u[2] = b0.z; u[3] = b0.w;
        u[4] = b1.x; u[5] = b1.y; u[6] = b1.z; u[7] = b1.w;
    }
    matmul8(zst, Wsa, nl, cg, u);
#pragma unroll
    for (int j = 0; j < 8; j++) {
        u[j] = fmaxf(u[j], 0.f);
        ust[cg + j][nl] = u[j];
    }
    __syncthreads();

    float o[8];
    {
        float4 b0 = *(const float4*)&bb[cg];
        float4 b1 = *(const float4*)&bb[cg + 4];
        o[0] = b0.x; o[1] = b0.y; o[2] = b0.z; o[3] = b0.w;
        o[4] = b1.x; o[5] = b1.y; o[6] = b1.z; o[7] = b1.w;
    }
    matmul8(ust, Wsb, nl, cg, o);

    if (valid) {
        *(float4*)&d_h2[(size_t)n * HH + cg]     = make_float4(o[0], o[1], o[2], o[3]);
        *(float4*)&d_h2[(size_t)n * HH + cg + 4] = make_float4(o[4], o[5], o[6], o[7]);
    }
    __syncthreads();   // zst/ust free -> reuse zst for stats reduction
    stats_reduce(o, valid, &zst[0][0], &zst[8][0], warp, lane,
                 &d_stats[2 * HH], &d_stats[3 * HH]);
}

// head (+ re-zero CSR state for next call) — round-11 form
__global__ void __launch_bounds__(256) k_head(
    const float* __restrict__ Wf1, const float* __restrict__ bf1,
    const float* __restrict__ Wf2, const float* __restrict__ bf2,
    const float* __restrict__ g2, const float* __restrict__ be2,
    float* __restrict__ outp) {
    __shared__ float gst[HH][NPB + 1];
    __shared__ float ust[HH][NPB + 1];
    __shared__ __align__(16) float W1s[HH][HH];
    __shared__ __align__(16) float W2s[HH][48];
    __shared__ float scl[HH], shf[HH];

    const int tid = threadIdx.x;
    const int base = blockIdx.x * NPB;

    {
        int g = blockIdx.x * 256 + tid;
        if (g < NN) d_counts[g] = 0;
        if (g < 256) d_partflag[g] = 0;
    }

    for (int i = tid; i < HH * HH; i += 256) W1s[i >> 5][i & 31] = Wf1[i];
    for (int i = tid; i < HH * 48; i += 256) {
        int k = i / 48, c = i % 48;
        W2s[k][c] = (c < CC) ? Wf2[k * CC + c] : 0.f;
    }
    if (tid < HH) {
        float m = d_stats[2 * HH + tid] * (1.f / NN);
        float v = d_stats[3 * HH + tid] * (1.f / NN) - m * m;
        float s = g2[tid] * rsqrtf(v + BN_EPS);
        scl[tid] = s;
        shf[tid] = be2[tid] - m * s;
    }
    __syncthreads();

    const int nl = tid >> 2;
    const int cg = (tid & 3) * 8;
    const int n = base + nl;
    const bool valid = n < NN;

    {
        float4 h0 = make_float4(0.f, 0.f, 0.f, 0.f), h1v = h0;
        if (valid) {
            h0  = *(const float4*)&d_h2[(size_t)n * HH + cg];
            h1v = *(const float4*)&d_h2[(size_t)n * HH + cg + 4];
        }
        gst[cg + 0][nl] = h0.x  * scl[cg + 0] + shf[cg + 0];
        gst[cg + 1][nl] = h0.y  * scl[cg + 1] + shf[cg + 1];
        gst[cg + 2][nl] = h0.z  * scl[cg + 2] + shf[cg + 2];
        gst[cg + 3][nl] = h0.w  * scl[cg + 3] + shf[cg + 3];
        gst[cg + 4][nl] = h1v.x * scl[cg + 4] + shf[cg + 4];
        gst[cg + 5][nl] = h1v.y * scl[cg + 5] + shf[cg + 5];
        gst[cg + 6][nl] = h1v.z * scl[cg + 6] + shf[cg + 6];
        gst[cg + 7][nl] = h1v.w * scl[cg + 7] + shf[cg + 7];
    }
    __syncthreads();

    float u[8];
    {
        float4 b0 = *(const float4*)&bf1[cg];
        float4 b1 = *(const float4*)&bf1[cg + 4];
        u[0] = b0.x; u[1] = b0.y; u[2] = b0.z; u[3] = b0.w;
        u[4] = b1.x; u[5] = b1.y; u[6] = b1.z; u[7] = b1.w;
    }
#pragma unroll
    for (int k = 0; k < HH; k++) {
        float zv = gst[k][nl];
        float4 w0 = *(const float4*)&W1s[k][cg];
        float4 w1 = *(const float4*)&W1s[k][cg + 4];
        u[0] += zv * w0.x; u[1] += zv * w0.y;
        u[2] += zv * w0.z; u[3] += zv * w0.w;
        u[4] += zv * w1.x; u[5] += zv * w1.y;
        u[6] += zv * w1.z; u[7] += zv * w1.w;
    }
#pragma unroll
    for (int j = 0; j < 8; j++) {
        u[j] = fmaxf(u[j], 0.f);
        ust[cg + j][nl] = u[j];
    }
    __syncthreads();

    const int cg2 = 32 + cg;
    const bool sec = (tid & 3) < 2;
    float o[8], o2[8];
#pragma unroll
    for (int j = 0; j < 8; j++) {
        int c = cg + j;
        o[j] = (c < CC) ? bf2[c] : 0.f;
        int c2 = cg2 + j;
        o2[j] = (sec && c2 < CC) ? bf2[c2] : 0.f;
    }
#pragma unroll
    for (int k = 0; k < HH; k++) {
        float zv = ust[k][nl];
        float4 w0 = *(const float4*)&W2s[k][cg];
        float4 w1 = *(const float4*)&W2s[k][cg + 4];
        o[0] += zv * w0.x; o[1] += zv * w0.y;
        o[2] += zv * w0.z; o[3] += zv * w0.w;
        o[4] += zv * w1.x; o[5] += zv * w1.y;
        o[6] += zv * w1.z; o[7] += zv * w1.w;
        if (sec) {
            float4 s0 = *(const float4*)&W2s[k][cg2];
            float4 s1 = *(const float4*)&W2s[k][cg2 + 4];
            o2[0] += zv * s0.x; o2[1] += zv * s0.y;
            o2[2] += zv * s0.z; o2[3] += zv * s0.w;
            o2[4] += zv * s1.x; o2[5] += zv * s1.y;
            o2[6] += zv * s1.z; o2[7] += zv * s1.w;
        }
    }
    if (valid) {
#pragma unroll
        for (int j = 0; j < 8; j++)
            outp[(size_t)n * CC + cg + j] = o[j];
        if (sec) {
#pragma unroll
            for (int j = 0; j < 8; j++) {
                int c2 = cg2 + j;
                if (c2 < CC) outp[(size_t)n * CC + c2] = o2[j];
            }
        }
    }
}

// ---------------- launcher ----------------------------------------------------
extern "C" void kernel_launch(void* const* d_in, const int* in_sizes, int n_in,
                              void* d_out, int out_size) {
    const float* x   = (const float*)d_in[0];
    const int*   row = (const int*)  d_in[1];
    const int*   col = (const int*)  d_in[2];
    const float* W1a = (const float*)d_in[3];
    const float* b1a = (const float*)d_in[4];
    const float* W1b = (const float*)d_in[5];
    const float* b1b = (const float*)d_in[6];
    const float* g1  = (const float*)d_in[7];
    const float* be1 = (const float*)d_in[8];
    const float* W2a = (const float*)d_in[9];
    const float* b2a = (const float*)d_in[10];
    const float* W2b = (const float*)d_in[11];
    const float* b2b = (const float*)d_in[12];
    const float* g2  = (const float*)d_in[13];
    const float* be2 = (const float*)d_in[14];
    const float* Wf1 = (const float*)d_in[15];
    const float* bf1 = (const float*)d_in[16];
    const float* Wf2 = (const float*)d_in[17];
    const float* bf2 = (const float*)d_in[18];
    float* out = (float*)d_out;

    static cudaStream_t sA = nullptr;
    static cudaEvent_t  evFork = nullptr, evJoin = nullptr;
    static bool inited = false;
    if (!inited) {
        cudaStreamCreateWithFlags(&sA, cudaStreamNonBlocking);
        cudaEventCreateWithFlags(&evFork, cudaEventDisableTiming);
        cudaEventCreateWithFlags(&evJoin, cudaEventDisableTiming);
        inited = true;
    }

    // fork: gemm1 (long pole) enqueued FIRST on sA; CSR build on main stream
    cudaEventRecord(evFork, 0);
    cudaStreamWaitEvent(sA, evFork, 0);

    k_gemm1<<<(NN + GT2 - 1) / GT2, 128, 0, sA>>>(x, W1a);

    const int eblk1 = (EE + 255) / 256;
    k_hist   <<<eblk1, 256, 0, 0>>>(row);
    k_scan   <<<NB_SCAN, 256, 0, 0>>>();
    k_scatter<<<eblk1, 256, 0, 0>>>(row, col);

    // join
    cudaEventRecord(evJoin, sA);
    cudaStreamWaitEvent(0, evJoin, 0);

    k_gin1<<<NB_GIN, 256, 0, 0>>>(b1a, W1b, b1b);
    k_gin2<<<NB_GIN, 256, 0, 0>>>(g1, be1, W2a, b2a, W2b, b2b);
    k_head<<<NB_GIN, 256, 0, 0>>>(Wf1, bf1, Wf2, bf2, g2, be2, out);
}

// round 17
// speedup vs baseline: 1.0905x; 1.0242x over previous
#include <cuda_runtime.h>

#define NN 50000
#define EE 800000
#define FF 602
#define HH 32
#define CC 41
#define BN_EPS 1e-5f
#define FULLMASK 0xffffffffu
#define NB_SCAN ((NN + 255) / 256)   // 196

#define KC 16                         // k-chunk for gemm1
#define GT2 64                        // rows per gemm1 block
#define XP 68                         // 64 + pad

#define NPB 64                        // nodes per gin/head block
#define NB_GIN ((NN + NPB - 1) / NPB) // 782
#define SCAP 2048                     // staged edge-index capacity per tile (8KB)

// ---------------- scratch (device globals) ----------------------------------
static __device__ float d_y  [NN * HH];
static __device__ float d_h1 [NN * HH];
static __device__ float d_h2 [NN * HH];
static __device__ float d_stats[4 * HH];
static __device__ int   d_counts[NN];     // zeroed by k_head each call (BSS=0 first call)
static __device__ int   d_rowptr[NN];
static __device__ int   d_cursor[NN];
static __device__ int   d_colsorted[EE];  // stores c*HH (pre-scaled)
static __device__ int   d_partsum[256];
static __device__ int   d_partflag[256];  // zeroed by k_head each call

// ---------------- K1: y = x @ W1a — 4x4 tile, double-buffered (round-11) ----
__global__ void __launch_bounds__(128) k_gemm1(const float* __restrict__ x,
                                               const float* __restrict__ W1a) {
    __shared__ float xs[2][KC][XP];
    __shared__ float Ws[2][KC][HH];

    const int tid = threadIdx.x;
    const int rg  = tid >> 3;
    const int cg  = (tid & 7) * 4;
    const int rowbase = blockIdx.x * GT2;

    const int kl = tid & 15;
    const int rl = tid >> 4;
    const int wk = tid >> 3;
    const int wc = (tid & 7) * 4;

    float acc[4][4];
#pragma unroll
    for (int i = 0; i < 4; i++)
#pragma unroll
        for (int j = 0; j < 4; j++) acc[i][j] = 0.f;

    float xr[8];
    float4 wr;

    {
        const bool kok = kl < FF;
#pragma unroll
        for (int p = 0; p < 8; p++) {
            int grow = rowbase + rl * 8 + p;
            xr[p] = (kok && grow < NN) ? x[(size_t)grow * FF + kl] : 0.f;
        }
        wr = (wk < FF) ? *(const float4*)&W1a[wk * HH + wc]
                       : make_float4(0.f, 0.f, 0.f, 0.f);
#pragma unroll
        for (int p = 0; p < 8; p++) xs[0][kl][rl * 8 + p] = xr[p];
        *(float4*)&Ws[0][wk][wc] = wr;
    }
    __syncthreads();

    int buf = 0;
    for (int kb = 0; kb < FF; kb += KC) {
        const int nb = kb + KC;
        const bool hasnext = nb < FF;
        if (hasnext) {
            const bool kok = (nb + kl) < FF;
#pragma unroll
            for (int p = 0; p < 8; p++) {
                int grow = rowbase + rl * 8 + p;
                xr[p] = (kok && grow < NN) ? x[(size_t)grow * FF + nb + kl] : 0.f;
            }
            wr = ((nb + wk) < FF) ? *(const float4*)&W1a[(nb + wk) * HH + wc]
                                  : make_float4(0.f, 0.f, 0.f, 0.f);
        }
#pragma unroll
        for (int k = 0; k < KC; k++) {
            float4 xv = *(const float4*)&xs[buf][k][rg * 4];
            float4 wv = *(const float4*)&Ws[buf][k][cg];
            acc[0][0] += xv.x * wv.x; acc[0][1] += xv.x * wv.y;
            acc[0][2] += xv.x * wv.z; acc[0][3] += xv.x * wv.w;
            acc[1][0] += xv.y * wv.x; acc[1][1] += xv.y * wv.y;
            acc[1][2] += xv.y * wv.z; acc[1][3] += xv.y * wv.w;
            acc[2][0] += xv.z * wv.x; acc[2][1] += xv.z * wv.y;
            acc[2][2] += xv.z * wv.z; acc[2][3] += xv.z * wv.w;
            acc[3][0] += xv.w * wv.x; acc[3][1] += xv.w * wv.y;
            acc[3][2] += xv.w * wv.z; acc[3][3] += xv.w * wv.w;
        }
        if (hasnext) {
            int nbuf = buf ^ 1;
#pragma unroll
            for (int p = 0; p < 8; p++) xs[nbuf][kl][rl * 8 + p] = xr[p];
            *(float4*)&Ws[nbuf][wk][wc] = wr;
            __syncthreads();
            buf = nbuf;
        }
    }
#pragma unroll
    for (int i = 0; i < 4; i++) {
        int row = rowbase + rg * 4 + i;
        if (row < NN)
            *(float4*)&d_y[(size_t)row * HH + cg] =
                make_float4(acc[i][0], acc[i][1], acc[i][2], acc[i][3]);
    }
}

// ---------------- CSR build: 1 edge/thread -----------------------------------
__global__ void k_hist(const int* __restrict__ row) {
    int e = blockIdx.x * 256 + threadIdx.x;
    if (e < EE) atomicAdd(&d_counts[row[e]], 1);
}

__global__ void k_scan() {
    __shared__ int sh[256];
    __shared__ int red[8];
    __shared__ int s_boff;
    const int tid = threadIdx.x, blk = blockIdx.x;

    if (blk == 0 && tid < 4 * HH) d_stats[tid] = 0.f;

    int i = blk * 256 + tid;
    int c = (i < NN) ? d_counts[i] : 0;
    sh[tid] = c;
    __syncthreads();
    for (int off = 1; off < 256; off <<= 1) {
        int t = (tid >= off) ? sh[tid - off] : 0;
        __syncthreads();
        sh[tid] += t;
        __syncthreads();
    }
    if (tid == 0) {
        d_partsum[blk] = sh[255];
        __threadfence();
        d_partflag[blk] = 1;
    }
    int acc = 0;
    for (int b = tid; b < blk; b += 256) {
        while (((volatile int*)d_partflag)[b] == 0) { }
        acc += ((volatile int*)d_partsum)[b];
    }
#pragma unroll
    for (int off = 16; off > 0; off >>= 1)
        acc += __shfl_down_sync(FULLMASK, acc, off);
    if ((tid & 31) == 0) red[tid >> 5] = acc;
    __syncthreads();
    if (tid == 0) {
        int t = 0;
#pragma unroll
        for (int w = 0; w < 8; w++) t += red[w];
        s_boff = t;
    }
    __syncthreads();
    int start = s_boff + sh[tid] - c;
    if (i < NN) { d_rowptr[i] = start; d_cursor[i] = start; }
}

__global__ void k_scatter(const int* __restrict__ row, const int* __restrict__ col) {
    int e = blockIdx.x * 256 + threadIdx.x;
    if (e >= EE) return;
    int r = row[e];
    int c = col[e];
    int p = atomicAdd(&d_cursor[r], 1);
    d_colsorted[p] = c * HH;              // pre-scaled
}

// ---------------- gathers (indices staged in smem) ---------------------------
__device__ __forceinline__ float gather_one(const float* __restrict__ src,
                                            const int* __restrict__ sidx,
                                            int deg, int lane) {
    float acc = 0.f;
    int j = 0;
    for (; j + 4 <= deg; j += 4) {
        int c0 = sidx[j], c1 = sidx[j + 1], c2 = sidx[j + 2], c3 = sidx[j + 3];
        acc += src[c0 + lane];
        acc += src[c1 + lane];
        acc += src[c2 + lane];
        acc += src[c3 + lane];
    }
    for (; j < deg; j++) acc += src[sidx[j] + lane];
    return acc;
}

// pair gather: nodes interleaved 4+4 loads (8 outstanding) over common prefix
__device__ __forceinline__ float2 gather_pair(const float* __restrict__ src,
                                              const int* __restrict__ s0, int d0,
                                              const int* __restrict__ s1, int d1,
                                              int lane) {
    float a0 = 0.f, a1 = 0.f;
    const int m = (d0 < d1) ? d0 : d1;
    int j = 0;
    for (; j + 4 <= m; j += 4) {
        int c00 = s0[j], c01 = s0[j + 1], c02 = s0[j + 2], c03 = s0[j + 3];
        int c10 = s1[j], c11 = s1[j + 1], c12 = s1[j + 2], c13 = s1[j + 3];
        float v00 = src[c00 + lane];
        float v10 = src[c10 + lane];
        float v01 = src[c01 + lane];
        float v11 = src[c11 + lane];
        float v02 = src[c02 + lane];
        float v12 = src[c12 + lane];
        float v03 = src[c03 + lane];
        float v13 = src[c13 + lane];
        a0 += v00; a1 += v10;
        a0 += v01; a1 += v11;
        a0 += v02; a1 += v12;
        a0 += v03; a1 += v13;
    }
    // tails (independent loads within each)
    int jj = j;
    for (; jj + 4 <= d0; jj += 4) {
        int c0 = s0[jj], c1 = s0[jj + 1], c2 = s0[jj + 2], c3 = s0[jj + 3];
        a0 += src[c0 + lane]; a0 += src[c1 + lane];
        a0 += src[c2 + lane]; a0 += src[c3 + lane];
    }
    for (; jj < d0; jj++) a0 += src[s0[jj] + lane];
    jj = j;
    for (; jj + 4 <= d1; jj += 4) {
        int c0 = s1[jj], c1 = s1[jj + 1], c2 = s1[jj + 2], c3 = s1[jj + 3];
        a1 += src[c0 + lane]; a1 += src[c1 + lane];
        a1 += src[c2 + lane]; a1 += src[c3 + lane];
    }
    for (; jj < d1; jj++) a1 += src[s1[jj] + lane];
    return make_float2(a0, a1);
}

// fallback (tile edge count > SCAP; statistically unreachable)
__device__ __forceinline__ float gather_slow(const float* __restrict__ src,
                                             int s0, int deg, int lane) {
    float acc = 0.f;
    for (int j = 0; j < deg; j++)
        acc += src[d_colsorted[s0 + j] + lane];
    return acc;
}

// tiled matvec: thread owns (node nl, cols cg..cg+7), z staged [k][node]
__device__ __forceinline__ void matmul8(const float (*zst)[NPB + 1],
                                        const float (*Ws)[HH],
                                        int nl, int cg, float o[8]) {
#pragma unroll
    for (int k = 0; k < HH; k++) {
        float zv = zst[k][nl];
        float4 w0 = *(const float4*)&Ws[k][cg];
        float4 w1 = *(const float4*)&Ws[k][cg + 4];
        o[0] += zv * w0.x; o[1] += zv * w0.y;
        o[2] += zv * w0.z; o[3] += zv * w0.w;
        o[4] += zv * w1.x; o[5] += zv * w1.y;
        o[6] += zv * w1.z; o[7] += zv * w1.w;
    }
}

// stats reduce into reused smem (caller must __syncthreads() before this)
__device__ __forceinline__ void stats_reduce(float o[8], bool valid,
                                             float* redS, float* redQ,
                                             int warp, int lane,
                                             float* gS, float* gQ) {
    float s[8], q[8];
#pragma unroll
    for (int j = 0; j < 8; j++) {
        float v = valid ? o[j] : 0.f;
        s[j] = v; q[j] = v * v;
    }
#pragma unroll
    for (int off = 16; off >= 4; off >>= 1)
#pragma unroll
        for (int j = 0; j < 8; j++) {
            s[j] += __shfl_down_sync(FULLMASK, s[j], off);
            q[j] += __shfl_down_sync(FULLMASK, q[j], off);
        }
    if (lane < 4) {
#pragma unroll
        for (int j = 0; j < 8; j++) {
            redS[warp * HH + lane * 8 + j] = s[j];
            redQ[warp * HH + lane * 8 + j] = q[j];
        }
    }
    __syncthreads();
    if (warp == 0) {
        float ts = 0.f, tq = 0.f;
#pragma unroll
        for (int w = 0; w < 8; w++) { ts += redS[w * HH + lane]; tq += redQ[w * HH + lane]; }
        atomicAdd(&gS[lane], ts);
        atomicAdd(&gQ[lane], tq);
    }
}

// per-warp staging of 8 nodes with pair-interleaved gathers
__device__ __forceinline__ void stage_gather8(const float* __restrict__ src,
                                              const int* __restrict__ sidx,
                                              int e_start, int cnt,
                                              int base, int warp, int lane,
                                              float zout[8], int degout[8]) {
#pragma unroll
    for (int i = 0; i < 8; i += 2) {
        int n0 = base + warp * 8 + i;
        int n1 = n0 + 1;
        float a0 = 0.f, a1 = 0.f;
        int d0 = 0, d1 = 0;
        if (n1 < NN) {
            int s0 = d_rowptr[n0]; d0 = d_counts[n0];
            int s1 = d_rowptr[n1]; d1 = d_counts[n1];
            int o0 = s0 - e_start, o1 = s1 - e_start;
            if (o1 + d1 <= cnt) {
                float2 r = gather_pair(src, sidx + o0, d0, sidx + o1, d1, lane);
                a0 = r.x; a1 = r.y;
            } else {
                a0 = gather_slow(src, s0, d0, lane);
                a1 = gather_slow(src, s1, d1, lane);
            }
        } else if (n0 < NN) {
            int s0 = d_rowptr[n0]; d0 = d_counts[n0];
            int o0 = s0 - e_start;
            a0 = (o0 + d0 <= cnt) ? gather_one(src, sidx + o0, d0, lane)
                                  : gather_slow(src, s0, d0, lane);
        }
        zout[i] = a0;     zout[i + 1] = a1;
        degout[i] = d0;   degout[i + 1] = d1;
    }
}

// conv1: h1 = relu(y[n] + agg(y) + b1a) @ W1b + b1b ; stats1
__global__ void __launch_bounds__(256) k_gin1(
    const float* __restrict__ ba, const float* __restrict__ Wb,
    const float* __restrict__ bb) {
    __shared__ float zst[HH][NPB + 1];
    __shared__ __align__(16) float Ws[HH][HH];
    __shared__ int sidx[SCAP];

    const int tid = threadIdx.x;
    const int warp = tid >> 5, lane = tid & 31;
    const int base = blockIdx.x * NPB;

    for (int i = tid; i < HH * HH; i += 256) Ws[i >> 5][i & 31] = Wb[i];

    const int e_start = d_rowptr[base];
    const int last = (base + NPB < NN) ? (base + NPB) : NN;
    const int e_end = (last < NN) ? d_rowptr[last] : EE;
    const int cnt = min(e_end - e_start, SCAP);
    for (int i = tid; i < cnt; i += 256) sidx[i] = d_colsorted[e_start + i];
    __syncthreads();

    const float baL = ba[lane];
    float zacc[8]; int zdeg[8];
    stage_gather8(d_y, sidx, e_start, cnt, base, warp, lane, zacc, zdeg);
#pragma unroll
    for (int i = 0; i < 8; i++) {
        int nl = warp * 8 + i;
        int n = base + nl;
        float z = 0.f;
        if (n < NN)
            z = fmaxf(d_y[(size_t)n * HH + lane] + zacc[i] + baL, 0.f);
        zst[lane][nl] = z;
    }
    __syncthreads();

    const int nl = tid >> 2;
    const int cg = (tid & 3) * 8;
    const int n = base + nl;
    const bool valid = n < NN;

    float o[8];
    float4 b0 = *(const float4*)&bb[cg];
    float4 b1 = *(const float4*)&bb[cg + 4];
    o[0] = b0.x; o[1] = b0.y; o[2] = b0.z; o[3] = b0.w;
    o[4] = b1.x; o[5] = b1.y; o[6] = b1.z; o[7] = b1.w;
    matmul8(zst, Ws, nl, cg, o);

    if (valid) {
        *(float4*)&d_h1[(size_t)n * HH + cg]     = make_float4(o[0], o[1], o[2], o[3]);
        *(float4*)&d_h1[(size_t)n * HH + cg + 4] = make_float4(o[4], o[5], o[6], o[7]);
    }
    __syncthreads();   // zst free -> reuse for stats reduction
    stats_reduce(o, valid, &zst[0][0], &zst[8][0], warp, lane,
                 &d_stats[0], &d_stats[HH]);
}

// conv2: BN1 folded; h2 = relu((t)@W2a+b2a)@W2b+b2b ; stats2
__global__ void __launch_bounds__(256) k_gin2(
    const float* __restrict__ g1, const float* __restrict__ be1,
    const float* __restrict__ Wa, const float* __restrict__ ba,
    const float* __restrict__ Wb, const float* __restrict__ bb) {
    __shared__ float zst[HH][NPB + 1];
    __shared__ float ust[HH][NPB + 1];
    __shared__ __align__(16) float Wsa[HH][HH];
    __shared__ __align__(16) float Wsb[HH][HH];
    __shared__ int sidx[SCAP];

    const int tid = threadIdx.x;
    const int warp = tid >> 5, lane = tid & 31;
    const int base = blockIdx.x * NPB;

    for (int i = tid; i < HH * HH; i += 256) {
        Wsa[i >> 5][i & 31] = Wa[i];
        Wsb[i >> 5][i & 31] = Wb[i];
    }

    const int e_start = d_rowptr[base];
    const int last = (base + NPB < NN) ? (base + NPB) : NN;
    const int e_end = (last < NN) ? d_rowptr[last] : EE;
    const int cnt = min(e_end - e_start, SCAP);
    for (int i = tid; i < cnt; i += 256) sidx[i] = d_colsorted[e_start + i];
    __syncthreads();

    float m = d_stats[lane] * (1.f / NN);
    float v = d_stats[HH + lane] * (1.f / NN) - m * m;
    float scale = g1[lane] * rsqrtf(v + BN_EPS);
    float shift = be1[lane] - m * scale;

    float zacc[8]; int zdeg[8];
    stage_gather8(d_h1, sidx, e_start, cnt, base, warp, lane, zacc, zdeg);
#pragma unroll
    for (int i = 0; i < 8; i++) {
        int nl = warp * 8 + i;
        int n = base + nl;
        float t = 0.f;
        if (n < NN) {
            float raw = zacc[i] + d_h1[(size_t)n * HH + lane];
            t = raw * scale + (float)(zdeg[i] + 1) * shift;
        }
        zst[lane][nl] = t;
    }
    __syncthreads();

    const int nl = tid >> 2;
    const int cg = (tid & 3) * 8;
    const int n = base + nl;
    const bool valid = n < NN;

    float u[8];
    {
        float4 b0 = *(const float4*)&ba[cg];
        float4 b1 = *(const float4*)&ba[cg + 4];
        u[0] = b0.x; u[1] = b0.y; u[2] = b0.z; u[3] = b0.w;
        u[4] = b1.x; u[5] = b1.y; u[6] = b1.z; u[7] = b1.w;
    }
    matmul8(zst, Wsa, nl, cg, u);
#pragma unroll
    for (int j = 0; j < 8; j++) {
        u[j] = fmaxf(u[j], 0.f);
        ust[cg + j][nl] = u[j];
    }
    __syncthreads();

    float o[8];
    {
        float4 b0 = *(const float4*)&bb[cg];
        float4 b1 = *(const float4*)&bb[cg + 4];
        o[0] = b0.x; o[1] = b0.y; o[2] = b0.z; o[3] = b0.w;
        o[4] = b1.x; o[5] = b1.y; o[6] = b1.z; o[7] = b1.w;
    }
    matmul8(ust, Wsb, nl, cg, o);

    if (valid) {
        *(float4*)&d_h2[(size_t)n * HH + cg]     = make_float4(o[0], o[1], o[2], o[3]);
        *(float4*)&d_h2[(size_t)n * HH + cg + 4] = make_float4(o[4], o[5], o[6], o[7]);
    }
    __syncthreads();   // reuse zst for stats reduction
    stats_reduce(o, valid, &zst[0][0], &zst[8][0], warp, lane,
                 &d_stats[2 * HH], &d_stats[3 * HH]);
}

// head (+ re-zero CSR state for next call)
__global__ void __launch_bounds__(256) k_head(
    const float* __restrict__ Wf1, const float* __restrict__ bf1,
    const float* __restrict__ Wf2, const float* __restrict__ bf2,
    const float* __restrict__ g2, const float* __restrict__ be2,
    float* __restrict__ outp) {
    __shared__ float gst[HH][NPB + 1];
    __shared__ float ust[HH][NPB + 1];
    __shared__ __align__(16) float W1s[HH][HH];
    __shared__ __align__(16) float W2s[HH][48];
    __shared__ float scl[HH], shf[HH];

    const int tid = threadIdx.x;
    const int base = blockIdx.x * NPB;

    {
        int g = blockIdx.x * 256 + tid;
        if (g < NN) d_counts[g] = 0;
        if (g < 256) d_partflag[g] = 0;
    }

    for (int i = tid; i < HH * HH; i += 256) W1s[i >> 5][i & 31] = Wf1[i];
    for (int i = tid; i < HH * 48; i += 256) {
        int k = i / 48, c = i % 48;
        W2s[k][c] = (c < CC) ? Wf2[k * CC + c] : 0.f;
    }
    if (tid < HH) {
        float m = d_stats[2 * HH + tid] * (1.f / NN);
        float v = d_stats[3 * HH + tid] * (1.f / NN) - m * m;
        float s = g2[tid] * rsqrtf(v + BN_EPS);
        scl[tid] = s;
        shf[tid] = be2[tid] - m * s;
    }
    __syncthreads();

    const int nl = tid >> 2;
    const int cg = (tid & 3) * 8;
    const int n = base + nl;
    const bool valid = n < NN;

    {
        float4 h0 = make_float4(0.f, 0.f, 0.f, 0.f), h1v = h0;
        if (valid) {
            h0  = *(const float4*)&d_h2[(size_t)n * HH + cg];
            h1v = *(const float4*)&d_h2[(size_t)n * HH + cg + 4];
        }
        gst[cg + 0][nl] = h0.x  * scl[cg + 0] + shf[cg + 0];
        gst[cg + 1][nl] = h0.y  * scl[cg + 1] + shf[cg + 1];
        gst[cg + 2][nl] = h0.z  * scl[cg + 2] + shf[cg + 2];
        gst[cg + 3][nl] = h0.w  * scl[cg + 3] + shf[cg + 3];
        gst[cg + 4][nl] = h1v.x * scl[cg + 4] + shf[cg + 4];
        gst[cg + 5][nl] = h1v.y * scl[cg + 5] + shf[cg + 5];
        gst[cg + 6][nl] = h1v.z * scl[cg + 6] + shf[cg + 6];
        gst[cg + 7][nl] = h1v.w * scl[cg + 7] + shf[cg + 7];
    }
    __syncthreads();

    float u[8];
    {
        float4 b0 = *(const float4*)&bf1[cg];
        float4 b1 = *(const float4*)&bf1[cg + 4];
        u[0] = b0.x; u[1] = b0.y; u[2] = b0.z; u[3] = b0.w;
        u[4] = b1.x; u[5] = b1.y; u[6] = b1.z; u[7] = b1.w;
    }
#pragma unroll
    for (int k = 0; k < HH; k++) {
        float zv = gst[k][nl];
        float4 w0 = *(const float4*)&W1s[k][cg];
        float4 w1 = *(const float4*)&W1s[k][cg + 4];
        u[0] += zv * w0.x; u[1] += zv * w0.y;
        u[2] += zv * w0.z; u[3] += zv * w0.w;
        u[4] += zv * w1.x; u[5] += zv * w1.y;
        u[6] += zv * w1.z; u[7] += zv * w1.w;
    }
#pragma unroll
    for (int j = 0; j < 8; j++) {
        u[j] = fmaxf(u[j], 0.f);
        ust[cg + j][nl] = u[j];
    }
    __syncthreads();

    const int cg2 = 32 + cg;
    const bool sec = (tid & 3) < 2;
    float o[8], o2[8];
#pragma unroll
    for (int j = 0; j < 8; j++) {
        int c = cg + j;
        o[j] = (c < CC) ? bf2[c] : 0.f;
        int c2 = cg2 + j;
        o2[j] = (sec && c2 < CC) ? bf2[c2] : 0.f;
    }
#pragma unroll
    for (int k = 0; k < HH; k++) {
        float zv = ust[k][nl];
        float4 w0 = *(const float4*)&W2s[k][cg];
        float4 w1 = *(const float4*)&W2s[k][cg + 4];
        o[0] += zv * w0.x; o[1] += zv * w0.y;
        o[2] += zv * w0.z; o[3] += zv * w0.w;
        o[4] += zv * w1.x; o[5] += zv * w1.y;
        o[6] += zv * w1.z; o[7] += zv * w1.w;
        if (sec) {
            float4 s0 = *(const float4*)&W2s[k][cg2];
            float4 s1 = *(const float4*)&W2s[k][cg2 + 4];
            o2[0] += zv * s0.x; o2[1] += zv * s0.y;
            o2[2] += zv * s0.z; o2[3] += zv * s0.w;
            o2[4] += zv * s1.x; o2[5] += zv * s1.y;
            o2[6] += zv * s1.z; o2[7] += zv * s1.w;
        }
    }
    if (valid) {
#pragma unroll
        for (int j = 0; j < 8; j++)
            outp[(size_t)n * CC + cg + j] = o[j];
        if (sec) {
#pragma unroll
            for (int j = 0; j < 8; j++) {
                int c2 = cg2 + j;
                if (c2 < CC) outp[(size_t)n * CC + c2] = o2[j];
            }
        }
    }
}

// ---------------- launcher ----------------------------------------------------
extern "C" void kernel_launch(void* const* d_in, const int* in_sizes, int n_in,
                              void* d_out, int out_size) {
    const float* x   = (const float*)d_in[0];
    const int*   row = (const int*)  d_in[1];
    const int*   col = (const int*)  d_in[2];
    const float* W1a = (const float*)d_in[3];
    const float* b1a = (const float*)d_in[4];
    const float* W1b = (const float*)d_in[5];
    const float* b1b = (const float*)d_in[6];
    const float* g1  = (const float*)d_in[7];
    const float* be1 = (const float*)d_in[8];
    const float* W2a = (const float*)d_in[9];
    const float* b2a = (const float*)d_in[10];
    const float* W2b = (const float*)d_in[11];
    const float* b2b = (const float*)d_in[12];
    const float* g2  = (const float*)d_in[13];
    const float* be2 = (const float*)d_in[14];
    const float* Wf1 = (const float*)d_in[15];
    const float* bf1 = (const float*)d_in[16];
    const float* Wf2 = (const float*)d_in[17];
    const float* bf2 = (const float*)d_in[18];
    float* out = (float*)d_out;

    static cudaStream_t sA = nullptr;
    static cudaEvent_t  evFork = nullptr, evJoin = nullptr;
    static bool inited = false;
    if (!inited) {
        cudaStreamCreateWithFlags(&sA, cudaStreamNonBlocking);
        cudaEventCreateWithFlags(&evFork, cudaEventDisableTiming);
        cudaEventCreateWithFlags(&evJoin, cudaEventDisableTiming);
        inited = true;
    }

    // fork: gemm1 (long pole) enqueued FIRST on sA; CSR build on main stream
    cudaEventRecord(evFork, 0);
    cudaStreamWaitEvent(sA, evFork, 0);

    k_gemm1<<<(NN + GT2 - 1) / GT2, 128, 0, sA>>>(x, W1a);

    const int eblk1 = (EE + 255) / 256;
    k_hist   <<<eblk1, 256, 0, 0>>>(row);
    k_scan   <<<NB_SCAN, 256, 0, 0>>>();
    k_scatter<<<eblk1, 256, 0, 0>>>(row, col);

    // join
    cudaEventRecord(evJoin, sA);
    cudaStreamWaitEvent(0, evJoin, 0);

    k_gin1<<<NB_GIN, 256, 0, 0>>>(b1a, W1b, b1b);
    k_gin2<<<NB_GIN, 256, 0, 0>>>(g1, be1, W2a, b2a, W2b, b2b);
    k_head<<<NB_GIN, 256, 0, 0>>>(Wf1, bf1, Wf2, bf2, g2, be2, out);
}